// round 15
// baseline (speedup 1.0000x reference)
#include <cuda_runtime.h>
#include <cuda_fp16.h>
#include <cstdint>

#define BB   2
#define NN   2048
#define DIMC 1024
#define HH   16
#define HD   64

// Scratch (allocation-free requirement)
__device__ float    g_q[BB*HH*NN*HD];       // fp32 q after projection
__device__ float    g_k[BB*HH*NN*HD];       // fp32 k after projection
__device__ uint32_t g_qh[BB*HH*NN*HD/2];    // q post-LN/RoPE, half2, QS-scaled
__device__ uint32_t g_kh[BB*HH*NN*HD/2];    // k post-LN/RoPE, half2
__device__ uint32_t g_vh[BB*HH*NN*HD/2];    // v half2 (packed in mm epilogue)
__device__ uint32_t g_xh[BB*NN*DIMC/2];     // x as half2 pairs  [4096][512]
__device__ uint32_t g_oh[BB*NN*DIMC/2];     // attn out as half2 [4096][512]
__device__ uint32_t g_wh[4*(DIMC/2)*DIMC];  // W{q,k,v,o} kpair-packed half2

// ---------------------------------------------------------------------------
__device__ __forceinline__ uint32_t f22u(float a, float b) {
    __half2 h = __floats2half2_rn(a, b);
    return *(uint32_t*)&h;
}
__device__ __forceinline__ float ex2(float x) {
    float y;
    asm("ex2.approx.f32 %0, %1;" : "=f"(y) : "f"(x));
    return y;
}
__device__ __forceinline__ void cp16(void* dst, const void* src) {
    uint32_t sa = (uint32_t)__cvta_generic_to_shared(dst);
    asm volatile("cp.async.cg.shared.global [%0], [%1], 16;"
                 :: "r"(sa), "l"(src));
}
#define CP_COMMIT() asm volatile("cp.async.commit_group;")
#define CP_WAIT(n)  asm volatile("cp.async.wait_group %0;" :: "n"(n))

#define MMA_F16(c, a0, a1, a2, a3, b0, b1)                                    \
    asm volatile(                                                             \
        "mma.sync.aligned.m16n8k16.row.col.f32.f16.f16.f32 "                  \
        "{%0,%1,%2,%3}, {%4,%5,%6,%7}, {%8,%9}, {%0,%1,%2,%3};"               \
        : "+f"((c)[0]), "+f"((c)[1]), "+f"((c)[2]), "+f"((c)[3])              \
        : "r"(a0), "r"(a1), "r"(a2), "r"(a3), "r"(b0), "r"(b1))

#define LDSM_X4_T(b, addr)                                                    \
    asm volatile(                                                             \
        "ldmatrix.sync.aligned.m8n8.x4.trans.shared.b16 {%0,%1,%2,%3}, [%4];" \
        : "=r"((b)[0]), "=r"((b)[1]), "=r"((b)[2]), "=r"((b)[3])              \
        : "r"(addr))

// ---------------------------------------------------------------------------
// Fused fp16 conversion: blocks [0,4096) convert x; [4096, 6144) convert W.
// ---------------------------------------------------------------------------
__global__ __launch_bounds__(256) void cvt_all(
    const float* __restrict__ x,
    const float* __restrict__ Wq, const float* __restrict__ Wk,
    const float* __restrict__ Wv, const float* __restrict__ Wo)
{
    if (blockIdx.x < 4096) {
        int i = blockIdx.x * 256 + threadIdx.x;        // 0..1048575
        float4 v = ((const float4*)x)[i];
        ((uint2*)g_xh)[i] = make_uint2(f22u(v.x, v.y), f22u(v.z, v.w));
    } else {
        int idx = (blockIdx.x - 4096) * 256 + threadIdx.x;   // 0..524287
        int mat = idx >> 17;
        int kp  = (idx >> 8) & 511;
        int c4  = idx & 255;
        const float* W = (mat == 0) ? Wq : (mat == 1) ? Wk
                       : (mat == 2) ? Wv : Wo;
        const float4 r0 = *(const float4*)(W + (size_t)(2*kp  )*DIMC + c4*4);
        const float4 r1 = *(const float4*)(W + (size_t)(2*kp+1)*DIMC + c4*4);
        uint4 o;
        o.x = f22u(r0.x, r1.x); o.y = f22u(r0.y, r1.y);
        o.z = f22u(r0.z, r1.z); o.w = f22u(r0.w, r1.w);
        *(uint4*)&g_wh[((size_t)mat*512 + kp)*DIMC + c4*4] = o;
    }
}

// ---------------------------------------------------------------------------
// fp16 m16n8k16 GEMM, 3-stage cp.async pipeline (unchanged).
// ---------------------------------------------------------------------------
#define MMW 20
#define BWW 136
#define ASZ (128*MMW)
#define BSZ (16*BWW)
#define MM_SMEM (3*(ASZ+BSZ)*4)   // 56832 B

__global__ __launch_bounds__(256, 2) void mm_mma(
    int mode,
    const float* __restrict__ bq, const float* __restrict__ bk,
    const float* __restrict__ bv, const float* __restrict__ bo,
    float* __restrict__ out)
{
    extern __shared__ __align__(16) uint32_t dsm[];
    uint32_t* As = dsm;
    uint32_t* Bs = dsm + 3*ASZ;

    const int tid = threadIdx.x, lane = tid & 31, w = tid >> 5;
    const int wm = w & 3, wn = w >> 2;
    const int rr = lane >> 2, qq = lane & 3;
    const int m0 = blockIdx.y * 128, c0 = blockIdx.x * 128;

    const uint32_t* Asrc = mode ? g_oh : g_xh;
    int mat, j0;
    if (mode == 1) { mat = 3; j0 = c0; }
    else           { mat = c0 >> 10; j0 = c0 & 1023; }
    const uint32_t* Bsrc = g_wh + (size_t)mat * 512 * DIMC;

    const int ra0 = tid >> 2,       ca0 = tid & 3;
    const int ra1 = (tid+256) >> 2, ca1 = (tid+256) & 3;
    const int kb0 = tid >> 5,       cb0 = tid & 31;
    const int kb1 = (tid+256) >> 5, cb1 = (tid+256) & 31;

    auto issue = [&](int kc, int s) {
        const int kp0 = kc * 16;
        cp16(&As[s*ASZ + ra0*MMW + ca0*4],
             Asrc + (size_t)(m0 + ra0)*512 + kp0 + ca0*4);
        cp16(&As[s*ASZ + ra1*MMW + ca1*4],
             Asrc + (size_t)(m0 + ra1)*512 + kp0 + ca1*4);
        cp16(&Bs[s*BSZ + kb0*BWW + cb0*4],
             Bsrc + (size_t)(kp0 + kb0)*DIMC + j0 + cb0*4);
        cp16(&Bs[s*BSZ + kb1*BWW + cb1*4],
             Bsrc + (size_t)(kp0 + kb1)*DIMC + j0 + cb1*4);
        CP_COMMIT();
    };

    float acc[2][8][4];
    #pragma unroll
    for (int mt = 0; mt < 2; mt++)
        #pragma unroll
        for (int nt = 0; nt < 8; nt++)
            #pragma unroll
            for (int e = 0; e < 4; e++) acc[mt][nt][e] = 0.f;

    issue(0, 0);
    issue(1, 1);

    for (int kc = 0; kc < DIMC/32; kc++) {
        if (kc < DIMC/32 - 2) { CP_WAIT(1); } else { CP_WAIT(0); }
        __syncthreads();

        const uint32_t* Ac = &As[(kc % 3)*ASZ];
        const uint32_t* Bc = &Bs[(kc % 3)*BSZ];
        #pragma unroll
        for (int ks = 0; ks < 2; ks++) {
            const int ku = ks * 8 + qq;
            uint32_t a[2][4];
            #pragma unroll
            for (int mt = 0; mt < 2; mt++) {
                int rm = wm*32 + mt*16 + rr;
                a[mt][0] = Ac[rm*MMW     + ku];
                a[mt][1] = Ac[(rm+8)*MMW + ku];
                a[mt][2] = Ac[rm*MMW     + ku + 4];
                a[mt][3] = Ac[(rm+8)*MMW + ku + 4];
            }
            #pragma unroll
            for (int nt = 0; nt < 8; nt++) {
                int cn = wn*64 + nt*8 + rr;
                uint32_t b0 = Bc[(ks*8 + qq)*BWW     + cn];
                uint32_t b1 = Bc[(ks*8 + qq + 4)*BWW + cn];
                MMA_F16(acc[0][nt], a[0][0], a[0][1], a[0][2], a[0][3], b0, b1);
                MMA_F16(acc[1][nt], a[1][0], a[1][1], a[1][2], a[1][3], b0, b1);
            }
        }

        if (kc + 2 < DIMC/32) issue(kc + 2, (kc + 2) % 3);
    }

    // Epilogue.  mode 0: q,k scatter as fp32; v packed half2 -> g_vh.
    #pragma unroll
    for (int mt = 0; mt < 2; mt++) {
        int r_lo = m0 + wm*32 + mt*16 + rr;
        int r_hi = r_lo + 8;
        #pragma unroll
        for (int nt = 0; nt < 8; nt++) {
            int c = c0 + wn*64 + nt*8 + qq*2;
            if (mode == 0) {
                int t = c % 192, h = c / 192, d = t & 63;
                int bz_lo = r_lo >> 11, n_lo = r_lo & (NN-1);
                int bz_hi = r_hi >> 11, n_hi = r_hi & (NN-1);
                if (t < 128) {
                    float bias0, bias1;
                    float* dst;
                    if (t < 64) { bias0 = bq[c];      bias1 = bq[c+1];      dst = g_q; }
                    else        { bias0 = bk[c-DIMC]; bias1 = bk[c-DIMC+1]; dst = g_k; }
                    size_t lo = (((size_t)bz_lo*HH + h)*NN + n_lo)*HD + d;
                    size_t hi = (((size_t)bz_hi*HH + h)*NN + n_hi)*HD + d;
                    dst[lo]   = acc[mt][nt][0] + bias0;
                    dst[lo+1] = acc[mt][nt][1] + bias1;
                    dst[hi]   = acc[mt][nt][2] + bias0;
                    dst[hi+1] = acc[mt][nt][3] + bias1;
                } else {
                    float bias0 = bv[c - 2*DIMC], bias1 = bv[c - 2*DIMC + 1];
                    g_vh[(((size_t)bz_lo*HH + h)*NN + n_lo)*32 + (d>>1)] =
                        f22u(acc[mt][nt][0] + bias0, acc[mt][nt][1] + bias1);
                    g_vh[(((size_t)bz_hi*HH + h)*NN + n_hi)*32 + (d>>1)] =
                        f22u(acc[mt][nt][2] + bias0, acc[mt][nt][3] + bias1);
                }
            } else {
                float2 lo = make_float2(acc[mt][nt][0] + bo[c],
                                        acc[mt][nt][1] + bo[c+1]);
                float2 hi = make_float2(acc[mt][nt][2] + bo[c],
                                        acc[mt][nt][3] + bo[c+1]);
                *(float2*)(out + (size_t)r_lo*DIMC + c) = lo;
                *(float2*)(out + (size_t)r_hi*DIMC + c) = hi;
            }
        }
    }
}

// ---------------------------------------------------------------------------
// LayerNorm + RoPE v3 (unchanged): half-warp per row, 2 rows/warp.
// ---------------------------------------------------------------------------
__global__ __launch_bounds__(256) void ln_rope(
    const float* __restrict__ qnw, const float* __restrict__ qnb,
    const float* __restrict__ knw, const float* __restrict__ knb,
    const float* __restrict__ cosb, const float* __restrict__ sinb)
{
    const int R = BB*HH*NN;
    const float QS = 0.125f * 1.4426950408889634f;
    int warp = (blockIdx.x * blockDim.x + threadIdx.x) >> 5;
    int lane = threadIdx.x & 31;
    int hw   = lane >> 4;
    int hl   = lane & 15;
    int r    = 2*warp + hw;
    int which = r >= R;
    int wr = r - (which ? R : 0);
    int bz = wr / (HH*NN);
    int n  = wr & (NN-1);

    const float* nw = which ? knw : qnw;
    const float* nb = which ? knb : qnb;
    const float* src = (which ? g_k : g_q) + (size_t)wr * HD;

    float4 xv = *(const float4*)(src + 4*hl);
    float sum = (xv.x + xv.y) + (xv.z + xv.w);
    float sq  = xv.x*xv.x + xv.y*xv.y + xv.z*xv.z + xv.w*xv.w;
    #pragma unroll
    for (int o = 8; o; o >>= 1) {
        sum += __shfl_xor_sync(0xffffffffu, sum, o);
        sq  += __shfl_xor_sync(0xffffffffu, sq,  o);
    }
    float mean = sum * (1.f/64.f);
    float var  = sq  * (1.f/64.f) - mean*mean;
    float inv  = rsqrtf(var + 1e-6f);
    float4 wv  = *(const float4*)(nw + 4*hl);
    float4 bvv = *(const float4*)(nb + 4*hl);
    float y0 = (xv.x - mean) * inv * wv.x + bvv.x;
    float y1 = (xv.y - mean) * inv * wv.y + bvv.y;
    float y2 = (xv.z - mean) * inv * wv.z + bvv.z;
    float y3 = (xv.w - mean) * inv * wv.w + bvv.w;

    float p0 = __shfl_xor_sync(0xffffffffu, y0, 8);
    float p1 = __shfl_xor_sync(0xffffffffu, y1, 8);
    float p2 = __shfl_xor_sync(0xffffffffu, y2, 8);
    float p3 = __shfl_xor_sync(0xffffffffu, y3, 8);
    float sgn = (hl & 8) ? 1.f : -1.f;

    size_t rbase = ((size_t)bz*NN + n) * HD;
    float4 cv = *(const float4*)(cosb + rbase + 4*hl);
    float4 sv = *(const float4*)(sinb + rbase + 4*hl);
    float o0 = y0*cv.x + sgn*p0*sv.x;
    float o1 = y1*cv.y + sgn*p1*sv.y;
    float o2 = y2*cv.z + sgn*p2*sv.z;
    float o3 = y3*cv.w + sgn*p3*sv.w;

    uint2 pk;
    if (!which) { pk = make_uint2(f22u(o0*QS, o1*QS), f22u(o2*QS, o3*QS)); }
    else        { pk = make_uint2(f22u(o0, o1),       f22u(o2, o3)); }
    *(uint2*)&((which ? g_kh : g_qh)[(size_t)wr*32 + 2*hl]) = pk;
}

// ---------------------------------------------------------------------------
// Flash attention v7: occupancy restructure.  256 threads / 8 warps, each
// warp owns 16 q-rows (1 mtile) -> per-warp regs ~130, 2 CTAs/SM, 16 warps
// to cover the S->softmax->PV dependency chain.  Same layouts as v6.
// ---------------------------------------------------------------------------
#define KST 36      // u32 stride for Kh / Vh rows (144 B)

__global__ __launch_bounds__(256, 2) void attn_mma()
{
    __shared__ __align__(16) uint32_t Kh[2][64*KST];
    __shared__ __align__(16) uint32_t Vh[2][64*KST];

    const int tid = threadIdx.x, lane = tid & 31, w = tid >> 5;   // w: 0..7
    const int bh = blockIdx.y;
    const int q0 = blockIdx.x * 128;
    const uint32_t* qh = g_qh + (size_t)bh * NN * 32;
    const uint32_t* kh = g_kh + (size_t)bh * NN * 32;
    const uint32_t* vh = g_vh + (size_t)bh * NN * 32;

    const int rr = lane >> 2;
    const int qq = lane & 3;

    // Q A-fragments: warp w owns rows q0 + w*16 .. +15
    uint32_t qf[4][4];
    {
        int rbase = q0 + w*16 + rr;
        #pragma unroll
        for (int ks = 0; ks < 4; ks++) {
            qf[ks][0] = qh[(size_t)rbase*32     + ks*8 + qq];
            qf[ks][1] = qh[(size_t)(rbase+8)*32 + ks*8 + qq];
            qf[ks][2] = qh[(size_t)rbase*32     + ks*8 + qq + 4];
            qf[ks][3] = qh[(size_t)(rbase+8)*32 + ks*8 + qq + 4];
        }
    }

    const int lm_base = (lane & 15)*KST + (lane >> 4)*4;

    auto issue = [&](int kt, int s) {
        const int k0 = kt * 64;
        #pragma unroll
        for (int i = 0; i < 2; i++) {
            int idx = tid + i*256;          // 0..511: r = idx>>3, c4 = idx&7
            int r = idx >> 3, c4 = idx & 7;
            cp16(&Kh[s][r*KST + c4*4], kh + (size_t)(k0 + r)*32 + c4*4);
            cp16(&Vh[s][r*KST + c4*4], vh + (size_t)(k0 + r)*32 + c4*4);
        }
        CP_COMMIT();
    };

    float l_lo = 0.f, l_hi = 0.f;
    float o[8][4];
    #pragma unroll
    for (int nt = 0; nt < 8; nt++)
        #pragma unroll
        for (int e = 0; e < 4; e++) o[nt][e] = 0.f;

    issue(0, 0);

    for (int kt = 0; kt < NN/64; kt++) {
        const int s = kt & 1;
        CP_WAIT(0);
        __syncthreads();
        if (kt + 1 < NN/64) issue(kt + 1, s ^ 1);

        // S = Q @ K^T for this warp's 16 rows
        float sc[8][4];
        #pragma unroll
        for (int nt = 0; nt < 8; nt++)
            #pragma unroll
            for (int e = 0; e < 4; e++) sc[nt][e] = 0.f;

        #pragma unroll
        for (int ks = 0; ks < 4; ks++) {
            #pragma unroll
            for (int nt = 0; nt < 8; nt++) {
                int cn = nt*8 + rr;
                uint32_t b0 = Kh[s][cn*KST + ks*8 + qq];
                uint32_t b1 = Kh[s][cn*KST + ks*8 + qq + 4];
                MMA_F16(sc[nt], qf[ks][0], qf[ks][1], qf[ks][2], qf[ks][3],
                        b0, b1);
            }
        }

        // Softmax numerators (no-max) + pack P
        uint32_t ph[8][2];
        float rs_lo = 0.f, rs_hi = 0.f;
        #pragma unroll
        for (int nt = 0; nt < 8; nt++) {
            float e0 = ex2(sc[nt][0]);
            float e1 = ex2(sc[nt][1]);
            float e2 = ex2(sc[nt][2]);
            float e3 = ex2(sc[nt][3]);
            rs_lo += e0 + e1;
            rs_hi += e2 + e3;
            ph[nt][0] = f22u(e0, e1);
            ph[nt][1] = f22u(e2, e3);
        }
        #pragma unroll
        for (int off = 1; off <= 2; off <<= 1) {
            rs_lo += __shfl_xor_sync(0xffffffffu, rs_lo, off);
            rs_hi += __shfl_xor_sync(0xffffffffu, rs_hi, off);
        }
        l_lo += rs_lo;
        l_hi += rs_hi;

        // O += P @ V via ldmatrix.trans
        #pragma unroll
        for (int g = 0; g < 4; g++) {
            #pragma unroll
            for (int ntp = 0; ntp < 4; ntp++) {
                uint32_t b[4];
                uint32_t addr = (uint32_t)__cvta_generic_to_shared(
                    &Vh[s][g*16*KST + ntp*8 + lm_base]);
                LDSM_X4_T(b, addr);
                MMA_F16(o[2*ntp],   ph[2*g][0], ph[2*g][1],
                                    ph[2*g+1][0], ph[2*g+1][1], b[0], b[1]);
                MMA_F16(o[2*ntp+1], ph[2*g][0], ph[2*g][1],
                                    ph[2*g+1][0], ph[2*g+1][1], b[2], b[3]);
            }
        }
    }

    // Finalize -> fp16 gathered layout
    const int b = bh >> 4, h = bh & 15;
    float inv_lo = 1.f / l_lo, inv_hi = 1.f / l_hi;
    int r_lo = q0 + w*16 + rr;
    int r_hi = r_lo + 8;
    uint32_t* po_lo = g_oh + (size_t)(b*NN + r_lo)*512 + h*32;
    uint32_t* po_hi = g_oh + (size_t)(b*NN + r_hi)*512 + h*32;
    #pragma unroll
    for (int nt = 0; nt < 8; nt++) {
        int cu = nt*4 + qq;
        po_lo[cu] = f22u(o[nt][0]*inv_lo, o[nt][1]*inv_lo);
        po_hi[cu] = f22u(o[nt][2]*inv_hi, o[nt][3]*inv_hi);
    }
}

// ---------------------------------------------------------------------------
extern "C" void kernel_launch(void* const* d_in, const int* in_sizes, int n_in,
                              void* d_out, int out_size)
{
    const float* x   = (const float*)d_in[0];
    const float* rc  = (const float*)d_in[1];
    const float* rs  = (const float*)d_in[2];
    const float* Wq  = (const float*)d_in[3];
    const float* bq  = (const float*)d_in[4];
    const float* Wk  = (const float*)d_in[5];
    const float* bk  = (const float*)d_in[6];
    const float* Wv  = (const float*)d_in[7];
    const float* bv  = (const float*)d_in[8];
    const float* qnw = (const float*)d_in[9];
    const float* qnb = (const float*)d_in[10];
    const float* knw = (const float*)d_in[11];
    const float* knb = (const float*)d_in[12];
    const float* Wo  = (const float*)d_in[13];
    const float* bo  = (const float*)d_in[14];
    float* out = (float*)d_out;

    cudaFuncSetAttribute(mm_mma,
                         cudaFuncAttributeMaxDynamicSharedMemorySize, MM_SMEM);

    cvt_all<<<6144, 256>>>(x, Wq, Wk, Wv, Wo);

    mm_mma<<<dim3(24, 32), 256, MM_SMEM>>>(0, bq, bk, bv, bo, out);

    const int warps2 = BB*HH*NN;               // (q+k rows) / 2 rows per warp
    ln_rope<<<warps2/8, 256>>>(qnw, qnb, knw, knb, rc, rs);

    attn_mma<<<dim3(NN/128, BB*HH), 256>>>();

    mm_mma<<<dim3(8, 32), 256, MM_SMEM>>>(1, bq, bk, bv, bo, out);
}

// round 16
// speedup vs baseline: 1.0658x; 1.0658x over previous
#include <cuda_runtime.h>
#include <cuda_fp16.h>
#include <cstdint>

#define BB   2
#define NN   2048
#define DIMC 1024
#define HH   16
#define HD   64

// Scratch (allocation-free requirement)
__device__ uint32_t g_qh[BB*HH*NN*HD/2];    // q post-LN/RoPE, half2, QS-scaled
__device__ uint32_t g_kh[BB*HH*NN*HD/2];    // k post-LN/RoPE, half2
__device__ uint32_t g_vh[BB*HH*NN*HD/2];    // v half2
__device__ uint32_t g_xh[BB*NN*DIMC/2];     // x as half2 pairs  [4096][512]
__device__ uint32_t g_oh[BB*NN*DIMC/2];     // attn out as half2 [4096][512]
__device__ uint32_t g_wh[4*(DIMC/2)*DIMC];  // W{q,k,v,o} kpair-packed half2

// ---------------------------------------------------------------------------
__device__ __forceinline__ uint32_t f22u(float a, float b) {
    __half2 h = __floats2half2_rn(a, b);
    return *(uint32_t*)&h;
}
__device__ __forceinline__ float ex2(float x) {
    float y;
    asm("ex2.approx.f32 %0, %1;" : "=f"(y) : "f"(x));
    return y;
}
__device__ __forceinline__ void cp16(void* dst, const void* src) {
    uint32_t sa = (uint32_t)__cvta_generic_to_shared(dst);
    asm volatile("cp.async.cg.shared.global [%0], [%1], 16;"
                 :: "r"(sa), "l"(src));
}
#define CP_COMMIT() asm volatile("cp.async.commit_group;")
#define CP_WAIT(n)  asm volatile("cp.async.wait_group %0;" :: "n"(n))

#define MMA_F16(c, a0, a1, a2, a3, b0, b1)                                    \
    asm volatile(                                                             \
        "mma.sync.aligned.m16n8k16.row.col.f32.f16.f16.f32 "                  \
        "{%0,%1,%2,%3}, {%4,%5,%6,%7}, {%8,%9}, {%0,%1,%2,%3};"               \
        : "+f"((c)[0]), "+f"((c)[1]), "+f"((c)[2]), "+f"((c)[3])              \
        : "r"(a0), "r"(a1), "r"(a2), "r"(a3), "r"(b0), "r"(b1))

#define LDSM_X4_T(b, addr)                                                    \
    asm volatile(                                                             \
        "ldmatrix.sync.aligned.m8n8.x4.trans.shared.b16 {%0,%1,%2,%3}, [%4];" \
        : "=r"((b)[0]), "=r"((b)[1]), "=r"((b)[2]), "=r"((b)[3])              \
        : "r"(addr))

// ---------------------------------------------------------------------------
// Fused fp16 conversion: blocks [0,4096) convert x; [4096, 6144) convert W.
// ---------------------------------------------------------------------------
__global__ __launch_bounds__(256) void cvt_all(
    const float* __restrict__ x,
    const float* __restrict__ Wq, const float* __restrict__ Wk,
    const float* __restrict__ Wv, const float* __restrict__ Wo)
{
    if (blockIdx.x < 4096) {
        int i = blockIdx.x * 256 + threadIdx.x;        // 0..1048575
        float4 v = ((const float4*)x)[i];
        ((uint2*)g_xh)[i] = make_uint2(f22u(v.x, v.y), f22u(v.z, v.w));
    } else {
        int idx = (blockIdx.x - 4096) * 256 + threadIdx.x;   // 0..524287
        int mat = idx >> 17;
        int kp  = (idx >> 8) & 511;
        int c4  = idx & 255;
        const float* W = (mat == 0) ? Wq : (mat == 1) ? Wk
                       : (mat == 2) ? Wv : Wo;
        const float4 r0 = *(const float4*)(W + (size_t)(2*kp  )*DIMC + c4*4);
        const float4 r1 = *(const float4*)(W + (size_t)(2*kp+1)*DIMC + c4*4);
        uint4 o;
        o.x = f22u(r0.x, r1.x); o.y = f22u(r0.y, r1.y);
        o.z = f22u(r0.z, r1.z); o.w = f22u(r0.w, r1.w);
        *(uint4*)&g_wh[((size_t)mat*512 + kp)*DIMC + c4*4] = o;
    }
}

// ---------------------------------------------------------------------------
// fp16 m16n8k16 GEMM, 3-stage cp.async pipeline.  mode 0 epilogue now fuses
// bias + per-head LayerNorm + RoPE and writes fp16 g_qh/g_kh/g_vh directly
// (each warp's 64-col segment is exactly one (head, q|k|v) 64-dim block;
// LN stats = quad reduction; RoPE partner d^32 = nt^4, same thread).
// ---------------------------------------------------------------------------
#define MMW 20
#define BWW 136
#define ASZ (128*MMW)
#define BSZ (16*BWW)
#define MM_SMEM (3*(ASZ+BSZ)*4)   // 56832 B

__global__ __launch_bounds__(256, 2) void mm_mma(
    int mode,
    const float* __restrict__ bq, const float* __restrict__ bk,
    const float* __restrict__ bv, const float* __restrict__ bo,
    const float* __restrict__ qnw, const float* __restrict__ qnb,
    const float* __restrict__ knw, const float* __restrict__ knb,
    const float* __restrict__ cosb, const float* __restrict__ sinb,
    float* __restrict__ out)
{
    extern __shared__ __align__(16) uint32_t dsm[];
    uint32_t* As = dsm;
    uint32_t* Bs = dsm + 3*ASZ;

    const int tid = threadIdx.x, lane = tid & 31, w = tid >> 5;
    const int wm = w & 3, wn = w >> 2;
    const int rr = lane >> 2, qq = lane & 3;
    const int m0 = blockIdx.y * 128, c0 = blockIdx.x * 128;

    const uint32_t* Asrc = mode ? g_oh : g_xh;
    int mat, j0;
    if (mode == 1) { mat = 3; j0 = c0; }
    else           { mat = c0 >> 10; j0 = c0 & 1023; }
    const uint32_t* Bsrc = g_wh + (size_t)mat * 512 * DIMC;

    const int ra0 = tid >> 2,       ca0 = tid & 3;
    const int ra1 = (tid+256) >> 2, ca1 = (tid+256) & 3;
    const int kb0 = tid >> 5,       cb0 = tid & 31;
    const int kb1 = (tid+256) >> 5, cb1 = (tid+256) & 31;

    auto issue = [&](int kc, int s) {
        const int kp0 = kc * 16;
        cp16(&As[s*ASZ + ra0*MMW + ca0*4],
             Asrc + (size_t)(m0 + ra0)*512 + kp0 + ca0*4);
        cp16(&As[s*ASZ + ra1*MMW + ca1*4],
             Asrc + (size_t)(m0 + ra1)*512 + kp0 + ca1*4);
        cp16(&Bs[s*BSZ + kb0*BWW + cb0*4],
             Bsrc + (size_t)(kp0 + kb0)*DIMC + j0 + cb0*4);
        cp16(&Bs[s*BSZ + kb1*BWW + cb1*4],
             Bsrc + (size_t)(kp0 + kb1)*DIMC + j0 + cb1*4);
        CP_COMMIT();
    };

    float acc[2][8][4];
    #pragma unroll
    for (int mt = 0; mt < 2; mt++)
        #pragma unroll
        for (int nt = 0; nt < 8; nt++)
            #pragma unroll
            for (int e = 0; e < 4; e++) acc[mt][nt][e] = 0.f;

    issue(0, 0);
    issue(1, 1);

    for (int kc = 0; kc < DIMC/32; kc++) {
        if (kc < DIMC/32 - 2) { CP_WAIT(1); } else { CP_WAIT(0); }
        __syncthreads();

        const uint32_t* Ac = &As[(kc % 3)*ASZ];
        const uint32_t* Bc = &Bs[(kc % 3)*BSZ];
        #pragma unroll
        for (int ks = 0; ks < 2; ks++) {
            const int ku = ks * 8 + qq;
            uint32_t a[2][4];
            #pragma unroll
            for (int mt = 0; mt < 2; mt++) {
                int rm = wm*32 + mt*16 + rr;
                a[mt][0] = Ac[rm*MMW     + ku];
                a[mt][1] = Ac[(rm+8)*MMW + ku];
                a[mt][2] = Ac[rm*MMW     + ku + 4];
                a[mt][3] = Ac[(rm+8)*MMW + ku + 4];
            }
            #pragma unroll
            for (int nt = 0; nt < 8; nt++) {
                int cn = wn*64 + nt*8 + rr;
                uint32_t b0 = Bc[(ks*8 + qq)*BWW     + cn];
                uint32_t b1 = Bc[(ks*8 + qq + 4)*BWW + cn];
                MMA_F16(acc[0][nt], a[0][0], a[0][1], a[0][2], a[0][3], b0, b1);
                MMA_F16(acc[1][nt], a[1][0], a[1][1], a[1][2], a[1][3], b0, b1);
            }
        }

        if (kc + 2 < DIMC/32) issue(kc + 2, (kc + 2) % 3);
    }

    // ---------------- Epilogue ----------------
    if (mode == 0) {
        const int seg = c0 + wn*64;            // 64-col segment start
        const int h = seg / 192, t0 = seg % 192;
        const int kind = t0 >> 6;              // 0=q, 1=k, 2=v
        const float* biasp = (kind == 0) ? (bq + seg)
                           : (kind == 1) ? (bk + seg - DIMC)
                                         : (bv + seg - 2*DIMC);
        #pragma unroll
        for (int mt = 0; mt < 2; mt++) {
            int m_lo = m0 + wm*32 + mt*16 + rr;
            int m_hi = m_lo + 8;
            int bz_lo = m_lo >> 11, n_lo = m_lo & (NN-1);
            int bz_hi = m_hi >> 11, n_hi = m_hi & (NN-1);
            if (kind == 2) {
                #pragma unroll
                for (int nt = 0; nt < 8; nt++) {
                    int d = nt*8 + qq*2;
                    float2 bb = *(const float2*)(biasp + d);
                    g_vh[(((size_t)bz_lo*HH + h)*NN + n_lo)*32 + (d>>1)] =
                        f22u(acc[mt][nt][0]+bb.x, acc[mt][nt][1]+bb.y);
                    g_vh[(((size_t)bz_hi*HH + h)*NN + n_hi)*32 + (d>>1)] =
                        f22u(acc[mt][nt][2]+bb.x, acc[mt][nt][3]+bb.y);
                }
            } else {
                const float* nwp = kind ? knw : qnw;
                const float* nbp = kind ? knb : qnb;
                // bias + LN statistics (row = 64 values over the 4-lane quad)
                float s_lo = 0.f, sq_lo = 0.f, s_hi = 0.f, sq_hi = 0.f;
                #pragma unroll
                for (int nt = 0; nt < 8; nt++) {
                    int d = nt*8 + qq*2;
                    float2 bb = *(const float2*)(biasp + d);
                    float a0 = acc[mt][nt][0] + bb.x;
                    float a1 = acc[mt][nt][1] + bb.y;
                    float a2 = acc[mt][nt][2] + bb.x;
                    float a3 = acc[mt][nt][3] + bb.y;
                    acc[mt][nt][0] = a0; acc[mt][nt][1] = a1;
                    acc[mt][nt][2] = a2; acc[mt][nt][3] = a3;
                    s_lo += a0 + a1; sq_lo += a0*a0 + a1*a1;
                    s_hi += a2 + a3; sq_hi += a2*a2 + a3*a3;
                }
                #pragma unroll
                for (int off = 1; off <= 2; off <<= 1) {
                    s_lo  += __shfl_xor_sync(0xffffffffu, s_lo,  off);
                    sq_lo += __shfl_xor_sync(0xffffffffu, sq_lo, off);
                    s_hi  += __shfl_xor_sync(0xffffffffu, s_hi,  off);
                    sq_hi += __shfl_xor_sync(0xffffffffu, sq_hi, off);
                }
                float mean_lo = s_lo * (1.f/64.f);
                float var_lo  = sq_lo * (1.f/64.f) - mean_lo*mean_lo;
                float inv_lo  = rsqrtf(var_lo + 1e-6f);
                float mean_hi = s_hi * (1.f/64.f);
                float var_hi  = sq_hi * (1.f/64.f) - mean_hi*mean_hi;
                float inv_hi  = rsqrtf(var_hi + 1e-6f);
                // normalize in place
                #pragma unroll
                for (int nt = 0; nt < 8; nt++) {
                    int d = nt*8 + qq*2;
                    float2 wv2 = *(const float2*)(nwp + d);
                    float2 bb2 = *(const float2*)(nbp + d);
                    acc[mt][nt][0] = (acc[mt][nt][0]-mean_lo)*inv_lo*wv2.x + bb2.x;
                    acc[mt][nt][1] = (acc[mt][nt][1]-mean_lo)*inv_lo*wv2.y + bb2.y;
                    acc[mt][nt][2] = (acc[mt][nt][2]-mean_hi)*inv_hi*wv2.x + bb2.x;
                    acc[mt][nt][3] = (acc[mt][nt][3]-mean_hi)*inv_hi*wv2.y + bb2.y;
                }
                // RoPE + pack fp16
                size_t rb_lo = ((size_t)bz_lo*NN + n_lo)*HD;
                size_t rb_hi = ((size_t)bz_hi*NN + n_hi)*HD;
                uint32_t* dsth = kind ? g_kh : g_qh;
                const float scale = kind ? 1.f
                                         : 0.125f * 1.4426950408889634f;
                uint32_t* p_lo = dsth + (((size_t)bz_lo*HH + h)*NN + n_lo)*32;
                uint32_t* p_hi = dsth + (((size_t)bz_hi*HH + h)*NN + n_hi)*32;
                #pragma unroll
                for (int nt = 0; nt < 8; nt++) {
                    int d = nt*8 + qq*2;
                    int ntp = nt ^ 4;
                    float sgn = (nt < 4) ? -1.f : 1.f;
                    float2 cv = *(const float2*)(cosb + rb_lo + d);
                    float2 sv = *(const float2*)(sinb + rb_lo + d);
                    float o0 = acc[mt][nt][0]*cv.x + sgn*acc[mt][ntp][0]*sv.x;
                    float o1 = acc[mt][nt][1]*cv.y + sgn*acc[mt][ntp][1]*sv.y;
                    float2 cv2 = *(const float2*)(cosb + rb_hi + d);
                    float2 sv2 = *(const float2*)(sinb + rb_hi + d);
                    float o2 = acc[mt][nt][2]*cv2.x + sgn*acc[mt][ntp][2]*sv2.x;
                    float o3 = acc[mt][nt][3]*cv2.y + sgn*acc[mt][ntp][3]*sv2.y;
                    p_lo[d>>1] = f22u(o0*scale, o1*scale);
                    p_hi[d>>1] = f22u(o2*scale, o3*scale);
                }
            }
        }
    } else {
        #pragma unroll
        for (int mt = 0; mt < 2; mt++) {
            int r_lo = m0 + wm*32 + mt*16 + rr;
            int r_hi = r_lo + 8;
            #pragma unroll
            for (int nt = 0; nt < 8; nt++) {
                int c = c0 + wn*64 + nt*8 + qq*2;
                float2 lo = make_float2(acc[mt][nt][0] + bo[c],
                                        acc[mt][nt][1] + bo[c+1]);
                float2 hi = make_float2(acc[mt][nt][2] + bo[c],
                                        acc[mt][nt][3] + bo[c+1]);
                *(float2*)(out + (size_t)r_lo*DIMC + c) = lo;
                *(float2*)(out + (size_t)r_hi*DIMC + c) = hi;
            }
        }
    }
}

// ---------------------------------------------------------------------------
// Flash attention v6 (reverted from v7): 128 threads / 4 warps, warp owns
// 32 q-rows (2 mtiles), K B-frags hoisted across both mtiles, cp.async
// double-buffered K/V staging, ldmatrix.trans for PV, no-max softmax.
// ---------------------------------------------------------------------------
#define KST 36      // u32 stride for Kh / Vh rows (144 B)

__global__ __launch_bounds__(128, 2) void attn_mma()
{
    __shared__ __align__(16) uint32_t Kh[2][64*KST];
    __shared__ __align__(16) uint32_t Vh[2][64*KST];

    const int tid = threadIdx.x, lane = tid & 31, w = tid >> 5;   // w: 0..3
    const int bh = blockIdx.y;
    const int q0 = blockIdx.x * 128;
    const uint32_t* qh = g_qh + (size_t)bh * NN * 32;
    const uint32_t* kh = g_kh + (size_t)bh * NN * 32;
    const uint32_t* vh = g_vh + (size_t)bh * NN * 32;

    const int rr = lane >> 2;
    const int qq = lane & 3;

    uint32_t qf[2][4][4];
    #pragma unroll
    for (int mt = 0; mt < 2; mt++) {
        int rbase = q0 + w*32 + mt*16 + rr;
        #pragma unroll
        for (int ks = 0; ks < 4; ks++) {
            qf[mt][ks][0] = qh[(size_t)rbase*32     + ks*8 + qq];
            qf[mt][ks][1] = qh[(size_t)(rbase+8)*32 + ks*8 + qq];
            qf[mt][ks][2] = qh[(size_t)rbase*32     + ks*8 + qq + 4];
            qf[mt][ks][3] = qh[(size_t)(rbase+8)*32 + ks*8 + qq + 4];
        }
    }

    const int lm_base = (lane & 15)*KST + (lane >> 4)*4;

    auto issue = [&](int kt, int s) {
        const int k0 = kt * 64;
        #pragma unroll
        for (int i = 0; i < 4; i++) {
            int idx = tid + i*128;
            int r = idx >> 3, c4 = idx & 7;
            cp16(&Kh[s][r*KST + c4*4], kh + (size_t)(k0 + r)*32 + c4*4);
            cp16(&Vh[s][r*KST + c4*4], vh + (size_t)(k0 + r)*32 + c4*4);
        }
        CP_COMMIT();
    };

    float l_i[2][2];
    float o[2][8][4];
    #pragma unroll
    for (int mt = 0; mt < 2; mt++) {
        l_i[mt][0] = 0.f; l_i[mt][1] = 0.f;
        #pragma unroll
        for (int nt = 0; nt < 8; nt++)
            #pragma unroll
            for (int e = 0; e < 4; e++) o[mt][nt][e] = 0.f;
    }

    issue(0, 0);

    for (int kt = 0; kt < NN/64; kt++) {
        const int s = kt & 1;
        CP_WAIT(0);
        __syncthreads();
        if (kt + 1 < NN/64) issue(kt + 1, s ^ 1);

        // S for BOTH m-tiles in one pass (K frags loaded once)
        float sc[2][8][4];
        #pragma unroll
        for (int mt = 0; mt < 2; mt++)
            #pragma unroll
            for (int nt = 0; nt < 8; nt++)
                #pragma unroll
                for (int e = 0; e < 4; e++) sc[mt][nt][e] = 0.f;

        #pragma unroll
        for (int ks = 0; ks < 4; ks++) {
            #pragma unroll
            for (int nt = 0; nt < 8; nt++) {
                int cn = nt*8 + rr;
                uint32_t b0 = Kh[s][cn*KST + ks*8 + qq];
                uint32_t b1 = Kh[s][cn*KST + ks*8 + qq + 4];
                MMA_F16(sc[0][nt], qf[0][ks][0], qf[0][ks][1],
                                   qf[0][ks][2], qf[0][ks][3], b0, b1);
                MMA_F16(sc[1][nt], qf[1][ks][0], qf[1][ks][1],
                                   qf[1][ks][2], qf[1][ks][3], b0, b1);
            }
        }

        uint32_t ph[2][8][2];
        #pragma unroll
        for (int mt = 0; mt < 2; mt++) {
            float rs_lo = 0.f, rs_hi = 0.f;
            #pragma unroll
            for (int nt = 0; nt < 8; nt++) {
                float e0 = ex2(sc[mt][nt][0]);
                float e1 = ex2(sc[mt][nt][1]);
                float e2 = ex2(sc[mt][nt][2]);
                float e3 = ex2(sc[mt][nt][3]);
                rs_lo += e0 + e1;
                rs_hi += e2 + e3;
                ph[mt][nt][0] = f22u(e0, e1);
                ph[mt][nt][1] = f22u(e2, e3);
            }
            #pragma unroll
            for (int off = 1; off <= 2; off <<= 1) {
                rs_lo += __shfl_xor_sync(0xffffffffu, rs_lo, off);
                rs_hi += __shfl_xor_sync(0xffffffffu, rs_hi, off);
            }
            l_i[mt][0] += rs_lo;
            l_i[mt][1] += rs_hi;
        }

        // O += P @ V via ldmatrix.trans
        #pragma unroll
        for (int g = 0; g < 4; g++) {
            #pragma unroll
            for (int ntp = 0; ntp < 4; ntp++) {
                uint32_t b[4];
                uint32_t addr = (uint32_t)__cvta_generic_to_shared(
                    &Vh[s][g*16*KST + ntp*8 + lm_base]);
                LDSM_X4_T(b, addr);
                MMA_F16(o[0][2*ntp],   ph[0][2*g][0], ph[0][2*g][1],
                                       ph[0][2*g+1][0], ph[0][2*g+1][1], b[0], b[1]);
                MMA_F16(o[1][2*ntp],   ph[1][2*g][0], ph[1][2*g][1],
                                       ph[1][2*g+1][0], ph[1][2*g+1][1], b[0], b[1]);
                MMA_F16(o[0][2*ntp+1], ph[0][2*g][0], ph[0][2*g][1],
                                       ph[0][2*g+1][0], ph[0][2*g+1][1], b[2], b[3]);
                MMA_F16(o[1][2*ntp+1], ph[1][2*g][0], ph[1][2*g][1],
                                       ph[1][2*g+1][0], ph[1][2*g+1][1], b[2], b[3]);
            }
        }
    }

    // Finalize -> fp16 gathered layout
    const int b = bh >> 4, h = bh & 15;
    #pragma unroll
    for (int mt = 0; mt < 2; mt++) {
        float inv_lo = 1.f / l_i[mt][0], inv_hi = 1.f / l_i[mt][1];
        int r_lo = q0 + w*32 + mt*16 + rr;
        int r_hi = r_lo + 8;
        uint32_t* po_lo = g_oh + (size_t)(b*NN + r_lo)*512 + h*32;
        uint32_t* po_hi = g_oh + (size_t)(b*NN + r_hi)*512 + h*32;
        #pragma unroll
        for (int nt = 0; nt < 8; nt++) {
            int cu = nt*4 + qq;
            po_lo[cu] = f22u(o[mt][nt][0]*inv_lo, o[mt][nt][1]*inv_lo);
            po_hi[cu] = f22u(o[mt][nt][2]*inv_hi, o[mt][nt][3]*inv_hi);
        }
    }
}

// ---------------------------------------------------------------------------
extern "C" void kernel_launch(void* const* d_in, const int* in_sizes, int n_in,
                              void* d_out, int out_size)
{
    const float* x   = (const float*)d_in[0];
    const float* rc  = (const float*)d_in[1];
    const float* rs  = (const float*)d_in[2];
    const float* Wq  = (const float*)d_in[3];
    const float* bq  = (const float*)d_in[4];
    const float* Wk  = (const float*)d_in[5];
    const float* bk  = (const float*)d_in[6];
    const float* Wv  = (const float*)d_in[7];
    const float* bv  = (const float*)d_in[8];
    const float* qnw = (const float*)d_in[9];
    const float* qnb = (const float*)d_in[10];
    const float* knw = (const float*)d_in[11];
    const float* knb = (const float*)d_in[12];
    const float* Wo  = (const float*)d_in[13];
    const float* bo  = (const float*)d_in[14];
    float* out = (float*)d_out;

    cudaFuncSetAttribute(mm_mma,
                         cudaFuncAttributeMaxDynamicSharedMemorySize, MM_SMEM);

    cvt_all<<<6144, 256>>>(x, Wq, Wk, Wv, Wo);

    mm_mma<<<dim3(24, 32), 256, MM_SMEM>>>(0, bq, bk, bv, bo,
                                           qnw, qnb, knw, knb, rc, rs, out);

    attn_mma<<<dim3(NN/128, BB*HH), 128>>>();

    mm_mma<<<dim3(8, 32), 256, MM_SMEM>>>(1, bq, bk, bv, bo,
                                          qnw, qnb, knw, knb, rc, rs, out);
}